// round 8
// baseline (speedup 1.0000x reference)
#include <cuda_runtime.h>

#define NU 200000
#define NI 100000
#define NN 300000
#define NE 1000000
#define NE2 2000000
#define SCAN_B 1024
#define NBLK ((NN + SCAN_B - 1) / SCAN_B)   // 293

// Scratch (device globals — no allocation allowed)
__device__ int      g_deg[NN];
__device__ int      g_rowptr[NN + 1];
__device__ int      g_cursor[NN];
__device__ int      g_adj[NE2];
__device__ float    g_dinv[NN];
__device__ float4   g_embA[NN * 16];   // P_L = dinv * e_L (f32, 256B rows). Holds P0, then P2.
__device__ float4   g_embB[NN * 16];   // Holds P1.
__device__ int      g_part[SCAN_B];

__global__ void k_count(const int* __restrict__ uid, const int* __restrict__ iid) {
    int e = blockIdx.x * blockDim.x + threadIdx.x;
    if (e < NE) {
        atomicAdd(&g_deg[uid[e]], 1);
        atomicAdd(&g_deg[NU + iid[e]], 1);
    }
}

// Block-local scan of degrees -> local-exclusive rowptr; block totals to g_part.
__global__ void k_scan1() {
    __shared__ int s[SCAN_B];
    int i = blockIdx.x * SCAN_B + threadIdx.x;
    int v = (i < NN) ? g_deg[i] : 0;
    s[threadIdx.x] = v;
    __syncthreads();
    for (int off = 1; off < SCAN_B; off <<= 1) {
        int t = (threadIdx.x >= off) ? s[threadIdx.x - off] : 0;
        __syncthreads();
        s[threadIdx.x] += t;
        __syncthreads();
    }
    if (i < NN) g_rowptr[i] = s[threadIdx.x] - v;
    if (threadIdx.x == SCAN_B - 1) g_part[blockIdx.x] = s[SCAN_B - 1];
}

// Every block redundantly scans the 293 partials, finalizes rowptr/cursor/dinv,
// then inits its slice of the f32 P0 table (P0 = dinv * e0).
__global__ void k_scan23(const float4* __restrict__ ue, const float4* __restrict__ ie) {
    __shared__ int s[SCAN_B];
    int tid = threadIdx.x, b = blockIdx.x;
    int pv = (tid < NBLK) ? g_part[tid] : 0;
    s[tid] = pv;
    __syncthreads();
    for (int off = 1; off < SCAN_B; off <<= 1) {
        int t = (tid >= off) ? s[tid - off] : 0;
        __syncthreads();
        s[tid] += t;
        __syncthreads();
    }
    int boff = (b > 0) ? s[b - 1] : 0;
    int i = b * SCAN_B + tid;
    if (i < NN) {
        int r = g_rowptr[i] + boff;
        g_rowptr[i] = r;
        g_cursor[i] = r;
        int d = g_deg[i];
        g_dinv[i] = (d > 0) ? rsqrtf((float)d) : 0.0f;
    }
    if (i == 0) g_rowptr[NN] = NE2;
    __syncthreads();
    int base = b * (SCAN_B * 16);
    for (int t = tid; t < SCAN_B * 16; t += SCAN_B) {
        int elem = base + t;
        if (elem < NN * 16) {
            float4 x = (elem < NU * 16) ? __ldg(&ue[elem]) : __ldg(&ie[elem - NU * 16]);
            float di = g_dinv[elem >> 4];
            g_embA[elem] = make_float4(di * x.x, di * x.y, di * x.z, di * x.w);
        }
    }
}

__global__ void k_fill(const int* __restrict__ uid, const int* __restrict__ iid) {
    int e = blockIdx.x * blockDim.x + threadIdx.x;
    if (e < NE) {
        int u  = uid[e];
        int it = NU + iid[e];
        g_adj[atomicAdd(&g_cursor[u], 1)]  = it;
        g_adj[atomicAdd(&g_cursor[it], 1)] = u;
    }
}

// Half-warp (16 lanes) per node; f32 rows (256B). Scalar-FADD inner loop so
// ptxas front-batches the unrolled LDG.128s (high MLP).
// !FINAL: write next table only (P_{L+1} = dinv^2 * sum). No out traffic.
//  FINAL: out = 0.25*(e0 + P1/dinv + P2/dinv + dinv*sum), single streamed write.
template <int SRC /*0:A->B 1:B->A*/, bool FINAL>
__global__ void __launch_bounds__(256) k_gather(float4* __restrict__ out,
                                                const float4* __restrict__ ue,
                                                const float4* __restrict__ ie) {
    int gt   = blockIdx.x * blockDim.x + threadIdx.x;
    int node = gt >> 4;
    if (node >= NN) return;
    int lane = gt & 15;

    const float4* __restrict__ sv = (SRC == 0) ? g_embA : g_embB;
    float4*       __restrict__ nv = (SRC == 0) ? g_embB : g_embA;

    int beg = g_rowptr[node];
    int end = g_rowptr[node + 1];

    float ax = 0.f, ay = 0.f, az = 0.f, aw = 0.f;
    for (int base = beg; base < end; base += 16) {
        int idx  = base + lane;
        int myid = (idx < end) ? g_adj[idx] : 0;
        int cnt  = min(16, end - base);
        #pragma unroll 8
        for (int k = 0; k < cnt; k++) {
            int s = __shfl_sync(0xffffffffu, myid, k, 16);
            float4 v = __ldg(&sv[s * 16 + lane]);
            ax += v.x; ay += v.y; az += v.z; aw += v.w;
        }
    }

    float wd  = g_dinv[node];
    int   off = node * 16 + lane;
    if (!FINAL) {
        float w2 = wd * wd;
        nv[off] = make_float4(w2 * ax, w2 * ay, w2 * az, w2 * aw);
    } else {
        float rd = (wd > 0.f) ? (1.0f / wd) : 0.0f;   // = sqrt(deg)
        float4 p1 = g_embB[off];                       // P1 = dinv*e1
        float4 p2 = sv[off];                           // P2 = dinv*e2 (src table, L2-hot)
        float4 e0 = (node < NU) ? __ldg(&ue[off]) : __ldg(&ie[off - NU * 16]);
        __stcs(&out[off], make_float4(
            0.25f * (e0.x + rd * (p1.x + p2.x) + wd * ax),
            0.25f * (e0.y + rd * (p1.y + p2.y) + wd * ay),
            0.25f * (e0.z + rd * (p1.z + p2.z) + wd * az),
            0.25f * (e0.w + rd * (p1.w + p2.w) + wd * aw)));
    }
}

extern "C" void kernel_launch(void* const* d_in, const int* in_sizes, int n_in,
                              void* d_out, int out_size) {
    const float4* ue  = (const float4*)d_in[0];   // user_emb [200000,64]
    const float4* ie  = (const float4*)d_in[1];   // item_emb [100000,64]
    const int*    uid = (const int*)d_in[2];      // user_ids [1M]
    const int*    iid = (const int*)d_in[3];      // item_ids [1M]
    float4*       out = (float4*)d_out;           // [300000,64]

    const int T = 256;

    void* deg_ptr = nullptr;
    cudaGetSymbolAddress(&deg_ptr, g_deg);
    cudaMemsetAsync(deg_ptr, 0, NN * sizeof(int));

    k_count <<<(NE + T - 1) / T, T>>>(uid, iid);
    k_scan1 <<<NBLK, SCAN_B>>>();
    k_scan23<<<NBLK, SCAN_B>>>(ue, ie);
    k_fill  <<<(NE + T - 1) / T, T>>>(uid, iid);

    dim3 g((NN * 16 + T - 1) / T);
    k_gather<0, false><<<g, T>>>(out, ue, ie);   // layer 1: A -> B (P1), no out traffic
    k_gather<1, false><<<g, T>>>(out, ue, ie);   // layer 2: B -> A (P2), no out traffic
    k_gather<0, true ><<<g, T>>>(out, ue, ie);   // layer 3: compose out in one pass
}

// round 9
// speedup vs baseline: 1.3183x; 1.3183x over previous
#include <cuda_runtime.h>

#define NU 200000
#define NI 100000
#define NN 300000
#define NE 1000000
#define NE2 2000000
#define SB 1024
#define GB 147                      // 147 * 2048 = 301056 >= NN; all blocks resident (<=148 SMs)

// Scratch (device globals — no allocation allowed)
__device__ int      g_deg[NN];
__device__ int      g_rowptr[NN + 1];
__device__ int      g_cursor[NN];
__device__ int      g_adj[NE2];
__device__ float    g_dinv[NN];
__device__ float4   g_embA[NN * 16];   // P_L = dinv * e_L (f32, 256B rows)
__device__ float4   g_embB[NN * 16];
__device__ int      g_part[GB];
__device__ int      g_bar;             // grid barrier counter (memset to 0 each launch)

__global__ void k_count(const int* __restrict__ uid, const int* __restrict__ iid) {
    int e = blockIdx.x * blockDim.x + threadIdx.x;
    if (e < NE) {
        atomicAdd(&g_deg[uid[e]], 1);
        atomicAdd(&g_deg[NU + iid[e]], 1);
    }
}

// ONE kernel: full scan of degrees (grid-wide barrier between block-scan and
// partial-combine), then rowptr/cursor/dinv finalize, then P0 + out init.
// Safe: all 147 blocks are co-resident, so the spin cannot livelock.
__global__ void __launch_bounds__(SB) k_scan_fused(const float4* __restrict__ ue,
                                                   const float4* __restrict__ ie,
                                                   float4* __restrict__ out) {
    __shared__ int s[SB];
    int b = blockIdx.x, tid = threadIdx.x;
    int n0 = b * 2048 + 2 * tid;                  // two consecutive nodes per thread
    int v0 = (n0     < NN) ? g_deg[n0]     : 0;
    int v1 = (n0 + 1 < NN) ? g_deg[n0 + 1] : 0;
    int pair = v0 + v1;
    s[tid] = pair;
    __syncthreads();
    for (int off = 1; off < SB; off <<= 1) {
        int t = (tid >= off) ? s[tid - off] : 0;
        __syncthreads();
        s[tid] += t;
        __syncthreads();
    }
    int excl = s[tid] - pair;                     // block-local exclusive prefix (pairs)
    int total = s[SB - 1];

    // publish block total, grid barrier
    if (tid == 0) {
        g_part[b] = total;
        __threadfence();
        atomicAdd(&g_bar, 1);
        while (atomicAdd(&g_bar, 0) < GB) { }
    }
    __syncthreads();

    // redundant scan of the 147 block totals
    int pv = (tid < GB) ? __ldcg(&g_part[tid]) : 0;
    __syncthreads();
    s[tid] = pv;
    __syncthreads();
    for (int off = 1; off < SB; off <<= 1) {
        int t = (tid >= off) ? s[tid - off] : 0;
        __syncthreads();
        s[tid] += t;
        __syncthreads();
    }
    int boff = (b > 0) ? s[b - 1] : 0;

    int r0 = boff + excl;
    if (n0 < NN) {
        g_rowptr[n0] = r0;
        g_cursor[n0] = r0;
        g_dinv[n0]   = (v0 > 0) ? rsqrtf((float)v0) : 0.0f;
    }
    if (n0 + 1 < NN) {
        g_rowptr[n0 + 1] = r0 + v0;
        g_cursor[n0 + 1] = r0 + v0;
        g_dinv[n0 + 1]   = (v1 > 0) ? rsqrtf((float)v1) : 0.0f;
    }
    if (b == 0 && tid == 0) g_rowptr[NN] = NE2;
    __syncthreads();

    // init P0 = dinv*e0 and out = 0.25*e0 for this block's 2048 nodes
    int base = b * 2048 * 16;
    for (int t = tid; t < 2048 * 16; t += SB) {
        int elem = base + t;
        if (elem < NN * 16) {
            float4 x = (elem < NU * 16) ? __ldg(&ue[elem]) : __ldg(&ie[elem - NU * 16]);
            float di = g_dinv[elem >> 4];
            g_embA[elem] = make_float4(di * x.x, di * x.y, di * x.z, di * x.w);
            __stcs(&out[elem], make_float4(0.25f * x.x, 0.25f * x.y, 0.25f * x.z, 0.25f * x.w));
        }
    }
}

__global__ void k_fill(const int* __restrict__ uid, const int* __restrict__ iid) {
    int e = blockIdx.x * blockDim.x + threadIdx.x;
    if (e < NE) {
        int u  = uid[e];
        int it = NU + iid[e];
        g_adj[atomicAdd(&g_cursor[u], 1)]  = it;
        g_adj[atomicAdd(&g_cursor[it], 1)] = u;
    }
}

// Half-warp (16 lanes) per node; f32 rows (256B); scalar FADD inner loop
// (proven-fastest config). All layers: out += 0.25*dinv*sum (ldcs/stcs RMW).
// WRITE_NEXT layers also store P_{L+1} = dinv^2 * sum.
template <int SRC /*0:A->B 1:B->A*/, bool WRITE_NEXT>
__global__ void __launch_bounds__(256) k_gather(float4* __restrict__ out) {
    int gt   = blockIdx.x * blockDim.x + threadIdx.x;
    int node = gt >> 4;
    if (node >= NN) return;
    int lane = gt & 15;
    unsigned hmask = (threadIdx.x & 16) ? 0xFFFF0000u : 0x0000FFFFu;

    const float4* __restrict__ sv = (SRC == 0) ? g_embA : g_embB;
    float4*       __restrict__ nv = (SRC == 0) ? g_embB : g_embA;

    int beg = g_rowptr[node];
    int end = g_rowptr[node + 1];

    float ax = 0.f, ay = 0.f, az = 0.f, aw = 0.f;
    for (int base = beg; base < end; base += 16) {
        int idx  = base + lane;
        int myid = (idx < end) ? g_adj[idx] : 0;
        int cnt  = min(16, end - base);
        #pragma unroll 8
        for (int k = 0; k < cnt; k++) {
            int s = __shfl_sync(hmask, myid, k, 16);
            float4 v = __ldg(&sv[s * 16 + lane]);
            ax += v.x; ay += v.y; az += v.z; aw += v.w;
        }
    }

    float wd  = g_dinv[node];
    int   off = node * 16 + lane;
    if (WRITE_NEXT) {
        float w2 = wd * wd;
        nv[off] = make_float4(w2 * ax, w2 * ay, w2 * az, w2 * aw);
    }
    float q = 0.25f * wd;
    float4 o = __ldcs(&out[off]);
    o.x += q * ax; o.y += q * ay; o.z += q * az; o.w += q * aw;
    __stcs(&out[off], o);
}

extern "C" void kernel_launch(void* const* d_in, const int* in_sizes, int n_in,
                              void* d_out, int out_size) {
    const float4* ue  = (const float4*)d_in[0];   // user_emb [200000,64]
    const float4* ie  = (const float4*)d_in[1];   // item_emb [100000,64]
    const int*    uid = (const int*)d_in[2];      // user_ids [1M]
    const int*    iid = (const int*)d_in[3];      // item_ids [1M]
    float4*       out = (float4*)d_out;           // [300000,64]

    const int T = 256;

    void* p = nullptr;
    cudaGetSymbolAddress(&p, g_deg);
    cudaMemsetAsync(p, 0, NN * sizeof(int));
    cudaGetSymbolAddress(&p, g_bar);
    cudaMemsetAsync(p, 0, sizeof(int));

    k_count     <<<(NE + T - 1) / T, T>>>(uid, iid);       // launch 0
    k_scan_fused<<<GB, SB>>>(ue, ie, out);                 // launch 1
    k_fill      <<<(NE + T - 1) / T, T>>>(uid, iid);       // launch 2

    dim3 g((NN * 16 + T - 1) / T);
    k_gather<0, true ><<<g, T>>>(out);   // launch 3  <-- profiled by ncu
    k_gather<1, true ><<<g, T>>>(out);   // launch 4
    k_gather<0, false><<<g, T>>>(out);   // launch 5
}